// round 1
// baseline (speedup 1.0000x reference)
#include <cuda_runtime.h>
#include <cuda_bf16.h>
#include <cstdint>

#define MAXN 100000
#define MAXE 1600000
#define DIN 256
#define F 64
#define TC 128  // 2*F combined columns

// ---------------- scratch (static device globals; no runtime alloc) ------
__device__ float  g_h [(size_t)MAXN * TC];   // [N][128]: cols 0..63 = h_high, 64..127 = h_low (post-leaky)
__device__ float  g_hp[(size_t)MAXN * TC];   // accumulators
__device__ float4 g_sc4[MAXN];               // per-node (s_hs, s_hd, s_ls, s_ld)
__device__ float2 g_rs[MAXN];                // (rowsum_high, rowsum_low)
__device__ float4 g_C[TC];                   // per-column folded coefficients
__device__ float  g_par[4];                  // inv_norm_high, inv_norm_low, theta_high, theta_low

__device__ __forceinline__ float lk(float x) { return x >= 0.0f ? x : 0.2f * x; }

// ---------------- K0: fold coefficients, norms, thetas -------------------
__global__ void k_prep(const float* __restrict__ ah, const float* __restrict__ al,
                       const float* __restrict__ ch, const float* __restrict__ cl) {
    __shared__ float sh[256], sl[256];
    int t = threadIdx.x;
    float vh = ah[t], vl = al[t];
    sh[t] = vh * vh;
    sl[t] = vl * vl;
    __syncthreads();
    for (int o = 128; o > 0; o >>= 1) {
        if (t < o) { sh[t] += sh[t + o]; sl[t] += sl[t + o]; }
        __syncthreads();
    }
    if (t == 0) {
        g_par[0] = 1.0f / sqrtf(sh[0]);
        g_par[1] = 1.0f / sqrtf(sl[0]);
        g_par[2] = (fminf(fmaxf(ch[0] + 3.0f, 0.0f), 6.0f) / 3.0f + 1e-6f) * 0.5f;
        g_par[3] = (fminf(fmaxf(cl[0] + 3.0f, 0.0f), 6.0f) / 3.0f + 1e-6f) * 0.5f;
    }
    if (t < F) {
        // high-h columns: contributes to all four node scalars
        float a0 = ah[t], a1 = ah[F + t], a2 = ah[2 * F + t], a3 = ah[3 * F + t];
        g_C[t] = make_float4(a0 + a2 + a3,   // s_hs coefficient (vh_s)
                             a1 + a2 - a3,   // s_hd coefficient (vh_d)
                             al[t],          // s_ls gets hh . al[:F]
                             al[F + t]);     // s_ld gets hh . al[F:2F]
    } else if (t < TC) {
        int c = t - F;
        float b2 = al[2 * F + c], b3 = al[3 * F + c];
        g_C[t] = make_float4(0.0f, 0.0f, b2 + b3, b2 - b3);  // low-h columns
    }
}

// ---------------- K1: zero accumulators ----------------------------------
__global__ void k_zero(int N) {
    int i = blockIdx.x * blockDim.x + threadIdx.x;
    if (i < N * (TC / 4)) reinterpret_cast<float4*>(g_hp)[i] = make_float4(0.f, 0.f, 0.f, 0.f);
    if (i < N) g_rs[i] = make_float2(0.f, 0.f);
}

// ---------------- K2: fused GEMM + leaky + per-node score scalars --------
// 64 rows per block, 256 threads. smem: input tile [64][256] (64KB) + W [256][128] (128KB).
__global__ __launch_bounds__(256, 1) void k_gemm(const float* __restrict__ input,
                                                 const float* __restrict__ Wh,
                                                 const float* __restrict__ Wl, int N) {
    extern __shared__ float smem[];
    float* sIn = smem;              // [64][256]
    float* sW  = smem + 64 * DIN;   // [256][128]
    int tid = threadIdx.x;
    int base = blockIdx.x * 64;

    // load combined W: cols 0..63 <- Wh, 64..127 <- Wl
    for (int idx = tid; idx < DIN * 16; idx += 256) {
        int k = idx >> 4;
        int c4 = (idx & 15) * 4;
        *reinterpret_cast<float4*>(&sW[k * TC + c4]) =
            *reinterpret_cast<const float4*>(&Wh[k * F + c4]);
        *reinterpret_cast<float4*>(&sW[k * TC + F + c4]) =
            *reinterpret_cast<const float4*>(&Wl[k * F + c4]);
    }
    // load input tile
    for (int idx = tid; idx < 64 * 64; idx += 256) {
        int r = idx >> 6;
        int k4 = (idx & 63) * 4;
        int n = base + r;
        float4 v = make_float4(0.f, 0.f, 0.f, 0.f);
        if (n < N) v = *reinterpret_cast<const float4*>(&input[(size_t)n * DIN + k4]);
        *reinterpret_cast<float4*>(&sIn[r * DIN + k4]) = v;
    }
    __syncthreads();

    int tx = tid & 31, ty = tid >> 5;  // lane, warp
    const float* aBase = &sIn[ty * 8 * DIN];
    const float* bBase = &sW[tx * 4];

    float acc[8][4];
#pragma unroll
    for (int j = 0; j < 8; j++)
#pragma unroll
        for (int c = 0; c < 4; c++) acc[j][c] = 0.0f;

#pragma unroll 4
    for (int k = 0; k < DIN; k++) {
        float4 b = *reinterpret_cast<const float4*>(&bBase[k * TC]);
#pragma unroll
        for (int j = 0; j < 8; j++) {
            float a = aBase[j * DIN + k];  // uniform within warp -> broadcast
            acc[j][0] += a * b.x;
            acc[j][1] += a * b.y;
            acc[j][2] += a * b.z;
            acc[j][3] += a * b.w;
        }
    }

    // epilogue: leaky, store h, fold score scalars with warp reduction
    float4 C0 = g_C[tx * 4 + 0], C1 = g_C[tx * 4 + 1],
           C2 = g_C[tx * 4 + 2], C3 = g_C[tx * 4 + 3];
#pragma unroll
    for (int j = 0; j < 8; j++) {
        int n = base + ty * 8 + j;
        float4 h;
        h.x = lk(acc[j][0]);
        h.y = lk(acc[j][1]);
        h.z = lk(acc[j][2]);
        h.w = lk(acc[j][3]);
        float4 p;
        p.x = h.x * C0.x + h.y * C1.x + h.z * C2.x + h.w * C3.x;
        p.y = h.x * C0.y + h.y * C1.y + h.z * C2.y + h.w * C3.y;
        p.z = h.x * C0.z + h.y * C1.z + h.z * C2.z + h.w * C3.z;
        p.w = h.x * C0.w + h.y * C1.w + h.z * C2.w + h.w * C3.w;
#pragma unroll
        for (int o = 16; o > 0; o >>= 1) {
            p.x += __shfl_down_sync(0xffffffffu, p.x, o);
            p.y += __shfl_down_sync(0xffffffffu, p.y, o);
            p.z += __shfl_down_sync(0xffffffffu, p.z, o);
            p.w += __shfl_down_sync(0xffffffffu, p.w, o);
        }
        if (n < N) {
            *reinterpret_cast<float4*>(&g_h[(size_t)n * TC + tx * 4]) = h;
            if (tx == 0) g_sc4[n] = p;
        }
    }
}

// ---------------- K3: edge pass (one warp per edge) ----------------------
__global__ __launch_bounds__(256) void k_edge(const int* __restrict__ edge, int E) {
    int w = (blockIdx.x * blockDim.x + threadIdx.x) >> 5;
    int lane = threadIdx.x & 31;
    if (w >= E) return;
    int src = edge[w];
    int dst = edge[E + w];

    float4 ss = g_sc4[src];
    float4 sd = g_sc4[dst];
    float sh = (ss.x + sd.y) * g_par[0];
    float sl = (ss.z + sd.w) * g_par[1];
    float eh = __expf(-lk(sh));
    float el = __expf(-lk(sl));

    float4 hv = *reinterpret_cast<const float4*>(&g_h[(size_t)dst * TC + lane * 4]);
    float wgt = (lane < 16) ? eh : el;  // lanes 0-15: high cols, 16-31: low cols
    float vx = hv.x * wgt, vy = hv.y * wgt, vz = hv.z * wgt, vw = hv.w * wgt;

    float* p = &g_hp[(size_t)src * TC + lane * 4];
    asm volatile("red.global.add.v4.f32 [%0], {%1, %2, %3, %4};"
                 :: "l"(p), "f"(vx), "f"(vy), "f"(vz), "f"(vw)
                 : "memory");
    if (lane == 0) {
        asm volatile("red.global.add.v2.f32 [%0], {%1, %2};"
                     :: "l"(&g_rs[src]), "f"(eh), "f"(el)
                     : "memory");
    }
}

// ---------------- K4: normalize + leaky + write output -------------------
__global__ void k_out(float* __restrict__ out, int N) {
    int i = blockIdx.x * blockDim.x + threadIdx.x;
    if (i >= N * (TC / 4)) return;
    int n = i >> 5;
    int q = i & 31;
    float2 rs = g_rs[n];
    float denom = (q < 16) ? (rs.x + g_par[2]) : (rs.y + g_par[3]);
    float inv = 1.0f / denom;
    float4 v = *reinterpret_cast<const float4*>(&g_hp[(size_t)n * TC + q * 4]);
    v.x = lk(v.x * inv);
    v.y = lk(v.y * inv);
    v.z = lk(v.z * inv);
    v.w = lk(v.w * inv);
    *reinterpret_cast<float4*>(&out[(size_t)n * TC + q * 4]) = v;
}

// ---------------- launch --------------------------------------------------
extern "C" void kernel_launch(void* const* d_in, const int* in_sizes, int n_in,
                              void* d_out, int out_size) {
    const float* input = (const float*)d_in[0];
    const int*   edge  = (const int*)d_in[1];
    const float* Wh    = (const float*)d_in[2];
    const float* Wl    = (const float*)d_in[3];
    const float* ah    = (const float*)d_in[4];
    const float* al    = (const float*)d_in[5];
    const float* ch    = (const float*)d_in[6];
    const float* cl    = (const float*)d_in[7];
    float* out = (float*)d_out;

    int N = in_sizes[0] / DIN;
    int E = in_sizes[1] / 2;

    const int GEMM_SMEM = (64 * DIN + DIN * TC) * (int)sizeof(float);  // 192 KB
    cudaFuncSetAttribute(k_gemm, cudaFuncAttributeMaxDynamicSharedMemorySize, GEMM_SMEM);

    k_prep<<<1, 256>>>(ah, al, ch, cl);
    {
        int threads = N * (TC / 4);  // covers both hp (float4) and rs zeroing
        k_zero<<<(threads + 255) / 256, 256>>>(N);
    }
    k_gemm<<<(N + 63) / 64, 256, GEMM_SMEM>>>(input, Wh, Wl, N);
    k_edge<<<(E + 7) / 8, 256>>>(edge, E);
    k_out<<<(N * (TC / 4) + 255) / 256, 256>>>(out, N);
}